// round 12
// baseline (speedup 1.0000x reference)
#include <cuda_runtime.h>
#include <stdint.h>

#define BB 32
#define C  256
#define H  56
#define OH 28
#define HP 58
#define EPSV 1e-5f
#define NPIX (BB*OH*OH)
#define NTI 14                 // 7 row-tiles x 2 col-tiles per image
#define NBLK (BB*NTI)          // 448

// ---------------- scratch ----------------
__device__ uint32_t g_x8u[BB*HP*HP*64];       // s8 sign(x), padded, channel-last
__device__ uint32_t g_w3f[72*16*32*4];        // frag-major W: [k32][mt16][lane32][4 u32]
__device__ uint32_t g_w1bits[2*C*8];          // 1x1 weight sign bits
__device__ float    g_pool[(size_t)NPIX*C];   // [pix][c]

// ---------------- s8 mma ----------------
__device__ __forceinline__ void mma_s8(int* c, const uint32_t* a, const uint32_t* b) {
    asm volatile(
        "mma.sync.aligned.m16n8k32.row.col.s32.s8.s8.s32 "
        "{%0,%1,%2,%3}, {%4,%5,%6,%7}, {%8,%9}, {%0,%1,%2,%3};"
        : "+r"(c[0]), "+r"(c[1]), "+r"(c[2]), "+r"(c[3])
        : "r"(a[0]), "r"(a[1]), "r"(a[2]), "r"(a[3]), "r"(b[0]), "r"(b[1]));
}
__device__ __forceinline__ void cpa16(uint32_t d, const void* s) {
    asm volatile("cp.async.cg.shared.global [%0], [%1], 16;" :: "r"(d), "l"(s));
}
#define CP_COMMIT() asm volatile("cp.async.commit_group;" ::: "memory")
#define CP_WAIT0()  asm volatile("cp.async.wait_group 0;" ::: "memory")
__device__ __forceinline__ uint32_t smem_u32(const void* p) {
    uint32_t a;
    asm("{ .reg .u64 t; cvta.to.shared.u64 t, %1; cvt.u32.u64 %0, t; }" : "=r"(a) : "l"(p));
    return a;
}

// ---------------- weight packing (frag-major W3 + bit-packed W1) ----------------
__global__ void pack_w(const float* __restrict__ w3, const float* __restrict__ w1) {
    int t = blockIdx.x*256 + threadIdx.x;
    if (t < 72*16*32*4) {
        int k32  = t >> 11;
        int rem  = t & 2047;
        int mt   = rem >> 7;
        int rem2 = rem & 127;
        int lane = rem2 >> 2;
        int r    = rem2 & 3;
        int g = lane >> 2, tg = lane & 3;
        int co  = mt*16 + g + (r & 1)*8;
        int tap = k32 >> 3, chq = k32 & 7;
        int chb = chq*32 + ((r >> 1) << 4) + tg*4;
        uint32_t pk = 0;
        #pragma unroll
        for (int z = 0; z < 4; z++) {
            float v = w3[((size_t)co*256 + chb + z)*9 + tap];
            int s = (v > 0.f) - (v < 0.f);
            pk |= ((uint32_t)(uint8_t)(int8_t)s) << (z*8);
        }
        g_w3f[t] = pk;
    } else if (t < 72*16*32*4 + 2*C*8) {
        int tt = t - 72*16*32*4;
        int co = tt >> 3, word = tt & 7;
        const float* p = w1 + (size_t)co*C + word*32;
        uint32_t bits = 0;
        #pragma unroll
        for (int j = 0; j < 32; j++)
            if (p[j] > 0.f) bits |= (1u << j);
        g_w1bits[tt] = bits;
    }
}

// ---------------- zero padded border of X8 ----------------
__global__ void border_zero() {
    int b = blockIdx.x, t = threadIdx.x;
    size_t base = (size_t)b*HP*HP*64;
    for (int i = t; i < HP*64; i += 256) {
        g_x8u[base + i] = 0;
        g_x8u[base + (size_t)(HP-1)*HP*64 + i] = 0;
    }
    for (int i = t; i < (HP-2)*64; i += 256) {
        int r = i >> 6, c = i & 63;
        g_x8u[base + (size_t)(r+1)*HP*64 + c] = 0;
        g_x8u[base + (size_t)(r+1)*HP*64 + (HP-1)*64 + c] = 0;
    }
}

// ---------------- fused s8-pack(sign(x)) + avgpool2x2 ----------------
__global__ void __launch_bounds__(256) packx8_pool(const float* __restrict__ x) {
    int tile = blockIdx.x;
    int i    = blockIdx.y;
    int b    = blockIdx.z;
    int tid = threadIdx.x, wid = tid >> 5, lane = tid & 31;

    __shared__ float    s_pool[7*256];
    __shared__ uint32_t s_s8[28*65];

    int r = lane / 14;
    int q = lane - r*14;
    bool active = (lane < 28);
    int rr = active ? r : 0;
    int row = 2*i + rr;
    int col = tile*14 + q;

    const float* xp = x + (((size_t)b*C + wid*32)*H + row)*H + col;

    uint32_t pk = 0;
    #pragma unroll
    for (int k = 0; k < 32; k++) {
        float v = active ? xp[(size_t)k*H*H] : 0.f;
        int s = (v > 0.f) - (v < 0.f);
        pk |= ((uint32_t)(uint8_t)(int8_t)s) << ((k & 3)*8);
        if ((k & 3) == 3) {
            if (active) s_s8[lane*65 + wid*8 + (k >> 2)] = pk;
            pk = 0;
        }
        float rs = v  + __shfl_down_sync(0xffffffffu, v, 14);
        float ps = rs + __shfl_down_sync(0xffffffffu, rs, 1);
        if (lane < 14 && (lane & 1) == 0)
            s_pool[(lane >> 1)*256 + wid*32 + k] = ps * 0.25f;
    }
    __syncthreads();

    for (int idx = tid; idx < 28*64; idx += 256) {
        int p = idx >> 6, c4 = idx & 63;
        int pr = p / 14, pq = p - pr*14;
        size_t rb = (((size_t)b*HP + (2*i + pr + 1))*HP + (tile*14 + pq + 1))*64;
        g_x8u[rb + c4] = s_s8[p*65 + c4];
    }
    for (int idx = tid; idx < 7*256; idx += 256) {
        int jl = idx >> 8, c = idx & 255;
        g_pool[ (((size_t)b*OH + i)*OH + tile*7 + jl)*C + c ] = s_pool[idx];
    }
}

// ---------------- IMMA conv3x3 (barrier-free mainloop) + epilogue ----------------
// Block = 4x16 spatial tile of output pixels (64), 256 threads, 8 warps.
// X window (9x33 cells x 256B) persists in smem; W A-frags via __ldg from L2.
// Pixel p = li*16+lj; MMA col index n*8+g -> li = n>>1, lj = (n&1)*8+g.
#define CSTRIDE 272                      // cell stride (256B data + 16 pad)
#define NCELL (9*33)                     // 297
#define XWIN_SZ (NCELL*CSTRIDE)          // 80784
#define OFF_SHB (256*66*4)               // 67584
#define SMEM_BYTES 80896

__global__ void __launch_bounds__(256, 2) conv_mma(
    const float* __restrict__ g3, const float* __restrict__ b3,
    const float* __restrict__ m3, const float* __restrict__ v3,
    const float* __restrict__ g1, const float* __restrict__ b1,
    const float* __restrict__ m1, const float* __restrict__ v1,
    float* __restrict__ out)
{
    extern __shared__ __align__(16) char smem[];
    uint32_t sb = smem_u32(smem);
    int tid = threadIdx.x, wid = tid >> 5, lane = tid & 31;
    int g = lane >> 2, tg = lane & 3;

    int bimg = blockIdx.x / NTI;
    int t14  = blockIdx.x - bimg*NTI;
    int i0 = (t14 >> 1) * 4;
    int j0 = (t14 & 1) * 16;

    // ---- load X window: rows 2*i0..+8, cols 2*j0..+32 (col clamped) ----
    {
        const char* xb = (const char*)g_x8u + (size_t)bimg*HP*HP*256;
        for (int idx = tid; idx < NCELL*16; idx += 256) {
            int cell = idx >> 4, sub = idx & 15;
            int r = cell / 33, c = cell - r*33;
            int rin = 2*i0 + r;
            int cin = 2*j0 + c; if (cin > HP-1) cin = HP-1;
            cpa16(sb + cell*CSTRIDE + sub*16,
                  xb + ((size_t)rin*HP + cin)*256 + sub*16);
        }
        CP_COMMIT();
        CP_WAIT0();
        __syncthreads();
    }

    int acc[2][8][4];
    #pragma unroll
    for (int m = 0; m < 2; m++)
        #pragma unroll
        for (int n = 0; n < 8; n++)
            #pragma unroll
            for (int k = 0; k < 4; k++) acc[m][n][k] = 0;

    // ---- barrier-free mainloop: 9 taps x 8 chq ----
    const uint4* wp = (const uint4*)g_w3f;
    int m0w = wid*2;
    for (int tap = 0; tap < 9; tap++) {
        int kh = tap / 3, kw = tap - kh*3;
        uint32_t bc[8];
        #pragma unroll
        for (int n = 0; n < 8; n++) {
            int row = 2*(n >> 1) + kh;
            int col = 2*((n & 1)*8 + g) + kw;
            bc[n] = (uint32_t)(row*33 + col)*CSTRIDE + tg*4;
        }
        #pragma unroll
        for (int chq = 0; chq < 8; chq++) {
            int k32 = tap*8 + chq;
            uint32_t a[2][4], b[8][2];
            #pragma unroll
            for (int m = 0; m < 2; m++) {
                uint4 av = __ldg(wp + ((size_t)(k32*16 + m0w + m)*32 + lane));
                a[m][0] = av.x; a[m][1] = av.y; a[m][2] = av.z; a[m][3] = av.w;
            }
            #pragma unroll
            for (int n = 0; n < 8; n++) {
                const char* pb = smem + bc[n] + chq*32;
                b[n][0] = *(const uint32_t*)pb;
                b[n][1] = *(const uint32_t*)(pb + 16);
            }
            #pragma unroll
            for (int m = 0; m < 2; m++)
                #pragma unroll
                for (int n = 0; n < 8; n++)
                    mma_s8(acc[m][n], a[m], b[n]);
        }
    }
    __syncthreads();   // X window dead; epilogue region reusable

    // ---- frag dump: acc -> s_dots[co][66] ----
    uint32_t* s_dots = (uint32_t*)smem;
    int m0 = wid*32;
    #pragma unroll
    for (int m = 0; m < 2; m++) {
        int co = m0 + m*16 + g;
        #pragma unroll
        for (int n = 0; n < 8; n++) {
            int px = n*8 + tg*2;
            *(uint2*)&s_dots[co*66 + px]     = make_uint2((uint32_t)acc[m][n][0], (uint32_t)acc[m][n][1]);
            *(uint2*)&s_dots[(co+8)*66 + px] = make_uint2((uint32_t)acc[m][n][2], (uint32_t)acc[m][n][3]);
        }
    }
    __syncthreads();

    // ---- pass2: BN3 + pool shortcut, h in place; sign bits ----
    float* s_hf = (float*)smem;
    uint32_t* s_hb = (uint32_t*)(smem + OFF_SHB);
    {
        int co = tid;
        float inv = g3[co] * rsqrtf(v3[co] + EPSV);
        float add = b3[co] - m3[co]*inv;
        #pragma unroll 4
        for (int px = 0; px < 64; px++) {
            int gi = i0 + (px >> 4);
            int gj = j0 + (px & 15); if (gj > 27) gj = 27;   // clamp (invalid px discarded later)
            int dot = (int)s_dots[co*66 + px];
            float hv = (float)dot*inv + add
                     + g_pool[(((size_t)bimg*OH + gi)*OH + gj)*C + co];
            s_hf[co*66 + px] = hv;
            uint32_t mk = __ballot_sync(0xffffffffu, hv > 0.f);
            if (lane == 0) s_hb[px*9 + wid] = mk;
        }
    }
    __syncthreads();

    // ---- phase C: XNOR 1x1 + BN + concat(h,h); masked stores ----
    uint32_t hb[2][8];
    #pragma unroll
    for (int pg = 0; pg < 2; pg++)
        #pragma unroll
        for (int w = 0; w < 8; w++)
            hb[pg][w] = s_hb[(pg*32 + lane)*9 + w];

    size_t ob[2]; bool val[2];
    #pragma unroll
    for (int pg = 0; pg < 2; pg++) {
        int px = pg*32 + lane;
        int gi = i0 + (px >> 4);
        int gj = j0 + (px & 15);
        val[pg] = (gj < 28);
        ob[pg] = (size_t)bimg*512*784 + gi*28 + (gj < 28 ? gj : 27);
    }

    const uint4* wtab = (const uint4*)g_w1bits;
    for (int co2 = wid; co2 < 512; co2 += 8) {
        uint4 w0  = __ldg(wtab + co2*2);
        uint4 w1q = __ldg(wtab + co2*2 + 1);
        float i1 = __ldg(g1 + co2) * rsqrtf(__ldg(v1 + co2) + EPSV);
        float a1 = __ldg(b1 + co2) - __ldg(m1 + co2)*i1;
        int hc = co2 & 255;
        #pragma unroll
        for (int pg = 0; pg < 2; pg++) {
            int P = 0;
            P += __popc(hb[pg][0] ^ w0.x);  P += __popc(hb[pg][1] ^ w0.y);
            P += __popc(hb[pg][2] ^ w0.z);  P += __popc(hb[pg][3] ^ w0.w);
            P += __popc(hb[pg][4] ^ w1q.x); P += __popc(hb[pg][5] ^ w1q.y);
            P += __popc(hb[pg][6] ^ w1q.z); P += __popc(hb[pg][7] ^ w1q.w);
            float hv = s_hf[hc*66 + pg*32 + lane];
            if (val[pg])
                out[ob[pg] + (size_t)co2*784] = (float)(256 - 2*P)*i1 + a1 + hv;
        }
    }
}

// ---------------- launch ----------------
extern "C" void kernel_launch(void* const* d_in, const int* in_sizes, int n_in,
                              void* d_out, int out_size) {
    const float* x  = (const float*)d_in[0];
    const float* w3 = (const float*)d_in[1];
    const float* g3 = (const float*)d_in[2];
    const float* b3 = (const float*)d_in[3];
    const float* m3 = (const float*)d_in[4];
    const float* v3 = (const float*)d_in[5];
    const float* w1 = (const float*)d_in[6];
    const float* g1 = (const float*)d_in[7];
    const float* b1 = (const float*)d_in[8];
    const float* m1 = (const float*)d_in[9];
    const float* v1 = (const float*)d_in[10];
    float* out = (float*)d_out;

    cudaFuncSetAttribute(conv_mma, cudaFuncAttributeMaxDynamicSharedMemorySize, SMEM_BYTES);

    pack_w<<<(72*16*32*4 + 2*C*8 + 255)/256, 256>>>(w3, w1);
    border_zero<<<BB, 256>>>();
    packx8_pool<<<dim3(4, OH, BB), 256>>>(x);
    conv_mma<<<NBLK, 256, SMEM_BYTES>>>(g3, b3, m3, v3, g1, b1, m1, v1, out);
}

// round 14
// speedup vs baseline: 1.1200x; 1.1200x over previous
#include <cuda_runtime.h>
#include <stdint.h>

#define BB 32
#define C  256
#define H  56
#define OH 28
#define HP 58
#define EPSV 1e-5f
#define NPIX (BB*OH*OH)     // 25088
#define NBLK (NPIX/64)      // 392

// ---------------- scratch ----------------
__device__ uint32_t g_x8u[BB*HP*HP*64];       // s8 sign(x), padded, channel-last
__device__ uint32_t g_w3f[72*16*32*4];        // frag-major W: [k32][mt16][lane32][4 u32]
__device__ uint32_t g_w1bits[2*C*8];          // 1x1 weight sign bits
__device__ float    g_pool[(size_t)NPIX*C];   // [pix][c]

// ---------------- s8 mma / ldmatrix ----------------
__device__ __forceinline__ void mma_s8(int* c, const uint32_t* a, const uint32_t* b) {
    asm volatile(
        "mma.sync.aligned.m16n8k32.row.col.s32.s8.s8.s32 "
        "{%0,%1,%2,%3}, {%4,%5,%6,%7}, {%8,%9}, {%0,%1,%2,%3};"
        : "+r"(c[0]), "+r"(c[1]), "+r"(c[2]), "+r"(c[3])
        : "r"(a[0]), "r"(a[1]), "r"(a[2]), "r"(a[3]), "r"(b[0]), "r"(b[1]));
}
__device__ __forceinline__ void ldsm4(uint32_t& r0, uint32_t& r1, uint32_t& r2, uint32_t& r3,
                                      uint32_t addr) {
    asm volatile("ldmatrix.sync.aligned.m8n8.x4.shared.b16 {%0,%1,%2,%3}, [%4];"
        : "=r"(r0), "=r"(r1), "=r"(r2), "=r"(r3) : "r"(addr));
}
__device__ __forceinline__ void cpa16(uint32_t d, const void* s) {
    asm volatile("cp.async.cg.shared.global [%0], [%1], 16;" :: "r"(d), "l"(s));
}
#define CP_COMMIT() asm volatile("cp.async.commit_group;" ::: "memory")
#define CP_WAIT2()  asm volatile("cp.async.wait_group 2;" ::: "memory")
__device__ __forceinline__ uint32_t smem_u32(const void* p) {
    uint32_t a;
    asm("{ .reg .u64 t; cvta.to.shared.u64 t, %1; cvt.u32.u64 %0, t; }" : "=r"(a) : "l"(p));
    return a;
}

// ---------------- weight packing (frag-major W3 + bit-packed W1) ----------------
__global__ void pack_w(const float* __restrict__ w3, const float* __restrict__ w1) {
    int t = blockIdx.x*256 + threadIdx.x;
    if (t < 72*16*32*4) {
        int k32  = t >> 11;
        int rem  = t & 2047;
        int mt   = rem >> 7;
        int rem2 = rem & 127;
        int lane = rem2 >> 2;
        int r    = rem2 & 3;
        int g = lane >> 2, tg = lane & 3;
        int co  = mt*16 + g + (r & 1)*8;
        int tap = k32 >> 3, chq = k32 & 7;
        int chb = chq*32 + ((r >> 1) << 4) + tg*4;
        uint32_t pk = 0;
        #pragma unroll
        for (int z = 0; z < 4; z++) {
            float v = w3[((size_t)co*256 + chb + z)*9 + tap];
            int s = (v > 0.f) - (v < 0.f);
            pk |= ((uint32_t)(uint8_t)(int8_t)s) << (z*8);
        }
        g_w3f[t] = pk;
    } else if (t < 72*16*32*4 + 2*C*8) {
        int tt = t - 72*16*32*4;
        int co = tt >> 3, word = tt & 7;
        const float* p = w1 + (size_t)co*C + word*32;
        uint32_t bits = 0;
        #pragma unroll
        for (int j = 0; j < 32; j++)
            if (p[j] > 0.f) bits |= (1u << j);
        g_w1bits[tt] = bits;
    }
}

// ---------------- zero padded border of X8 ----------------
__global__ void border_zero() {
    int b = blockIdx.x, t = threadIdx.x;
    size_t base = (size_t)b*HP*HP*64;
    for (int i = t; i < HP*64; i += 256) {
        g_x8u[base + i] = 0;
        g_x8u[base + (size_t)(HP-1)*HP*64 + i] = 0;
    }
    for (int i = t; i < (HP-2)*64; i += 256) {
        int r = i >> 6, c = i & 63;
        g_x8u[base + (size_t)(r+1)*HP*64 + c] = 0;
        g_x8u[base + (size_t)(r+1)*HP*64 + (HP-1)*64 + c] = 0;
    }
}

// ---------------- fused s8-pack(sign(x)) + avgpool2x2 ----------------
__global__ void __launch_bounds__(256) packx8_pool(const float* __restrict__ x) {
    int tile = blockIdx.x;
    int i    = blockIdx.y;
    int b    = blockIdx.z;
    int tid = threadIdx.x, wid = tid >> 5, lane = tid & 31;

    __shared__ float    s_pool[7*256];
    __shared__ uint32_t s_s8[28*65];

    int r = lane / 14;
    int q = lane - r*14;
    bool active = (lane < 28);
    int rr = active ? r : 0;
    int row = 2*i + rr;
    int col = tile*14 + q;

    const float* xp = x + (((size_t)b*C + wid*32)*H + row)*H + col;

    uint32_t pk = 0;
    #pragma unroll
    for (int k = 0; k < 32; k++) {
        float v = active ? xp[(size_t)k*H*H] : 0.f;
        int s = (v > 0.f) - (v < 0.f);
        pk |= ((uint32_t)(uint8_t)(int8_t)s) << ((k & 3)*8);
        if ((k & 3) == 3) {
            if (active) s_s8[lane*65 + wid*8 + (k >> 2)] = pk;
            pk = 0;
        }
        float rs = v  + __shfl_down_sync(0xffffffffu, v, 14);
        float ps = rs + __shfl_down_sync(0xffffffffu, rs, 1);
        if (lane < 14 && (lane & 1) == 0)
            s_pool[(lane >> 1)*256 + wid*32 + k] = ps * 0.25f;
    }
    __syncthreads();

    for (int idx = tid; idx < 28*64; idx += 256) {
        int p = idx >> 6, c4 = idx & 63;
        int pr = p / 14, pq = p - pr*14;
        size_t rb = (((size_t)b*HP + (2*i + pr + 1))*HP + (tile*14 + pq + 1))*64;
        g_x8u[rb + c4] = s_s8[p*65 + c4];
    }
    for (int idx = tid; idx < 7*256; idx += 256) {
        int jl = idx >> 8, c = idx & 255;
        g_pool[ (((size_t)b*OH + i)*OH + tile*7 + jl)*C + c ] = s_pool[idx];
    }
}

// ---------------- IMMA conv3x3 + BN + pool + XNOR 1x1 + BN + concat ----------------
// Block = 64 pixels x 256 co, 256 threads. cp.async 4-buffer depth-3 pipeline,
// LDS.128 A-frags, ldmatrix.x4 B-frags. Epilogue in-place in the dots region.
#define WBUF_SZ 16384                   // 2 k32-steps x [mt16][lane32][16B]
#define XBUF_SZ (64*80)                 // 64 pix rows, 80B stride (64B data)
#define BUF_SZ  (WBUF_SZ + XBUF_SZ)     // 21504
#define OFF_SHB (256*66*4)              // 67584 (dots/h region)
#define SMEM_BYTES (4*BUF_SZ)           // 86016 (>= 67584 + 2304 epilogue)

__global__ void __launch_bounds__(256, 2) conv_mma(
    const float* __restrict__ g3, const float* __restrict__ b3,
    const float* __restrict__ m3, const float* __restrict__ v3,
    const float* __restrict__ g1, const float* __restrict__ b1,
    const float* __restrict__ m1, const float* __restrict__ v1,
    float* __restrict__ out)
{
    extern __shared__ __align__(16) char smem[];
    uint32_t sb = smem_u32(smem);
    int tid = threadIdx.x, wid = tid >> 5, lane = tid & 31;
    int g = lane >> 2, tg = lane & 3;
    int p0 = blockIdx.x * 64;

    // staging geometry: thread t stages pixel t>>2, 16B-quarter t&3
    int pixrel = tid >> 2;
    int zi = tid & 3;
    int pixs = p0 + pixrel;
    int bbs = pixs / 784;
    int rms = pixs - bbs*784;
    int iis = rms / 28;
    int jjs = rms - iis*28;
    const char* xrow = (const char*)g_x8u + ((((size_t)bbs*HP + 2*iis)*HP + 2*jjs) << 8);

    // ldmatrix per-lane row offsets: matrix mi = lane>>3, row ri = lane&7.
    // LDSM.x4 #q covers b[2q][0..1], b[2q+1][0..1]:
    //   pixel = (2q + (mi>>1))*8 + ri, chunk = 2*ks + (mi&1)
    int mi = lane >> 3, ri = lane & 7;
    uint32_t loff[4];
    #pragma unroll
    for (int q = 0; q < 4; q++)
        loff[q] = (uint32_t)(((2*q + (mi >> 1))*8 + ri)*80 + (mi & 1)*16);

    int acc[2][8][4];
    #pragma unroll
    for (int m = 0; m < 2; m++)
        #pragma unroll
        for (int n = 0; n < 8; n++)
            #pragma unroll
            for (int k = 0; k < 4; k++) acc[m][n][k] = 0;

    #define ISSUE(s) do { \
        int tap_ = (s) >> 2, chunk_ = (s) & 3; \
        int kh_ = tap_ / 3, kw_ = tap_ - kh_*3; \
        uint32_t bd = sb + ((s) & 3)*BUF_SZ; \
        const char* ws_ = (const char*)g_w3f + (size_t)(s)*16384; \
        cpa16(bd + (uint32_t)tid*16,         ws_ + (size_t)tid*16); \
        cpa16(bd + (uint32_t)(tid+256)*16,   ws_ + (size_t)(tid+256)*16); \
        cpa16(bd + (uint32_t)(tid+512)*16,   ws_ + (size_t)(tid+512)*16); \
        cpa16(bd + (uint32_t)(tid+768)*16,   ws_ + (size_t)(tid+768)*16); \
        cpa16(bd + WBUF_SZ + (uint32_t)pixrel*80 + zi*16, \
              xrow + (kh_*HP + kw_)*256 + chunk_*64 + zi*16); \
    } while (0)

    ISSUE(0); CP_COMMIT();
    ISSUE(1); CP_COMMIT();
    ISSUE(2); CP_COMMIT();

    for (int s = 0; s < 36; s++) {
        CP_WAIT2();
        __syncthreads();
        if (s + 3 < 36) ISSUE(s + 3);
        CP_COMMIT();

        const char* Bf = smem + (s & 3)*BUF_SZ;
        uint32_t XbU = sb + (s & 3)*BUF_SZ + WBUF_SZ;
        #pragma unroll
        for (int ks = 0; ks < 2; ks++) {
            uint32_t a[2][4], b[8][2];
            #pragma unroll
            for (int m = 0; m < 2; m++) {
                uint4 av = *(const uint4*)(Bf + ks*8192 + (wid*2 + m)*512 + lane*16);
                a[m][0] = av.x; a[m][1] = av.y; a[m][2] = av.z; a[m][3] = av.w;
            }
            #pragma unroll
            for (int q = 0; q < 4; q++)
                ldsm4(b[2*q][0], b[2*q][1], b[2*q+1][0], b[2*q+1][1],
                      XbU + loff[q] + ks*32);
            #pragma unroll
            for (int m = 0; m < 2; m++)
                #pragma unroll
                for (int n = 0; n < 8; n++)
                    mma_s8(acc[m][n], a[m], b[n]);
        }
    }
    __syncthreads();   // buffers dead; dots region reusable

    // ---- frag dump: acc -> s_dots[co][66] ----
    uint32_t* s_dots = (uint32_t*)smem;
    int m0 = wid*32;
    #pragma unroll
    for (int m = 0; m < 2; m++) {
        int co = m0 + m*16 + g;
        #pragma unroll
        for (int n = 0; n < 8; n++) {
            int px = n*8 + tg*2;
            *(uint2*)&s_dots[co*66 + px]     = make_uint2((uint32_t)acc[m][n][0], (uint32_t)acc[m][n][1]);
            *(uint2*)&s_dots[(co+8)*66 + px] = make_uint2((uint32_t)acc[m][n][2], (uint32_t)acc[m][n][3]);
        }
    }
    __syncthreads();

    // ---- pass2: BN3 + pool shortcut, h written IN PLACE; sign bits ----
    float* s_hf = (float*)smem;
    uint32_t* s_hb = (uint32_t*)(smem + OFF_SHB);
    {
        int co = tid;
        float inv = g3[co] * rsqrtf(v3[co] + EPSV);
        float add = b3[co] - m3[co]*inv;
        #pragma unroll 4
        for (int px = 0; px < 64; px++) {
            int dot = (int)s_dots[co*66 + px];
            float hv = (float)dot*inv + add + g_pool[(size_t)(p0 + px)*C + co];
            s_hf[co*66 + px] = hv;
            uint32_t mk = __ballot_sync(0xffffffffu, hv > 0.f);
            if (lane == 0) s_hb[px*9 + wid] = mk;
        }
    }
    __syncthreads();

    // ---- phase C: XNOR 1x1 + BN + concat(h,h) ----
    uint32_t hb[2][8];
    #pragma unroll
    for (int pg = 0; pg < 2; pg++)
        #pragma unroll
        for (int w = 0; w < 8; w++)
            hb[pg][w] = s_hb[(pg*32 + lane)*9 + w];

    size_t ob[2];
    #pragma unroll
    for (int pg = 0; pg < 2; pg++) {
        int p = p0 + pg*32 + lane;
        int b2 = p / 784;
        int rm2 = p - b2*784;
        ob[pg] = (size_t)b2*512*784 + rm2;
    }

    const uint4* wtab = (const uint4*)g_w1bits;
    for (int co2 = wid; co2 < 512; co2 += 8) {
        uint4 w0  = __ldg(wtab + co2*2);
        uint4 w1q = __ldg(wtab + co2*2 + 1);
        float i1 = __ldg(g1 + co2) * rsqrtf(__ldg(v1 + co2) + EPSV);
        float a1 = __ldg(b1 + co2) - __ldg(m1 + co2)*i1;
        int hc = co2 & 255;
        #pragma unroll
        for (int pg = 0; pg < 2; pg++) {
            int P = 0;
            P += __popc(hb[pg][0] ^ w0.x);  P += __popc(hb[pg][1] ^ w0.y);
            P += __popc(hb[pg][2] ^ w0.z);  P += __popc(hb[pg][3] ^ w0.w);
            P += __popc(hb[pg][4] ^ w1q.x); P += __popc(hb[pg][5] ^ w1q.y);
            P += __popc(hb[pg][6] ^ w1q.z); P += __popc(hb[pg][7] ^ w1q.w);
            float hv = s_hf[hc*66 + pg*32 + lane];
            out[ob[pg] + (size_t)co2*784] = (float)(256 - 2*P)*i1 + a1 + hv;
        }
    }
}

// ---------------- launch ----------------
extern "C" void kernel_launch(void* const* d_in, const int* in_sizes, int n_in,
                              void* d_out, int out_size) {
    const float* x  = (const float*)d_in[0];
    const float* w3 = (const float*)d_in[1];
    const float* g3 = (const float*)d_in[2];
    const float* b3 = (const float*)d_in[3];
    const float* m3 = (const float*)d_in[4];
    const float* v3 = (const float*)d_in[5];
    const float* w1 = (const float*)d_in[6];
    const float* g1 = (const float*)d_in[7];
    const float* b1 = (const float*)d_in[8];
    const float* m1 = (const float*)d_in[9];
    const float* v1 = (const float*)d_in[10];
    float* out = (float*)d_out;

    cudaFuncSetAttribute(conv_mma, cudaFuncAttributeMaxDynamicSharedMemorySize, SMEM_BYTES);

    pack_w<<<(72*16*32*4 + 2*C*8 + 255)/256, 256>>>(w3, w1);
    border_zero<<<BB, 256>>>();
    packx8_pool<<<dim3(4, OH, BB), 256>>>(x);
    conv_mma<<<NBLK, 256, SMEM_BYTES>>>(g3, b3, m3, v3, g1, b1, m1, v1, out);
}

// round 17
// speedup vs baseline: 1.2870x; 1.1492x over previous
#include <cuda_runtime.h>
#include <stdint.h>

#define BB 32
#define C  256
#define H  56
#define OH 28
#define HP 58
#define EPSV 1e-5f
#define NPIX (BB*OH*OH)     // 25088
#define NBLK (NPIX/64)      // 392

// ---------------- scratch ----------------
__device__ uint32_t g_x8u[BB*HP*HP*64];       // s8 sign(x), padded, channel-last
__device__ uint32_t g_w3f[72*16*32*4];        // frag-major W: [k32][mt16][lane32][4 u32]
__device__ uint32_t g_w1bits[2*C*8];          // 1x1 weight sign bits
__device__ float    g_pool[(size_t)NPIX*C];   // [pix][c]

// ---------------- s8 mma / ldmatrix ----------------
__device__ __forceinline__ void mma_s8(int* c, const uint32_t* a, const uint32_t* b) {
    asm volatile(
        "mma.sync.aligned.m16n8k32.row.col.s32.s8.s8.s32 "
        "{%0,%1,%2,%3}, {%4,%5,%6,%7}, {%8,%9}, {%0,%1,%2,%3};"
        : "+r"(c[0]), "+r"(c[1]), "+r"(c[2]), "+r"(c[3])
        : "r"(a[0]), "r"(a[1]), "r"(a[2]), "r"(a[3]), "r"(b[0]), "r"(b[1]));
}
__device__ __forceinline__ void ldsm4(uint32_t& r0, uint32_t& r1, uint32_t& r2, uint32_t& r3,
                                      uint32_t addr) {
    asm volatile("ldmatrix.sync.aligned.m8n8.x4.shared.b16 {%0,%1,%2,%3}, [%4];"
        : "=r"(r0), "=r"(r1), "=r"(r2), "=r"(r3) : "r"(addr));
}
__device__ __forceinline__ void cpa16(uint32_t d, const void* s) {
    asm volatile("cp.async.cg.shared.global [%0], [%1], 16;" :: "r"(d), "l"(s));
}
#define CP_COMMIT() asm volatile("cp.async.commit_group;" ::: "memory")
#define CP_WAIT2()  asm volatile("cp.async.wait_group 2;" ::: "memory")
__device__ __forceinline__ uint32_t smem_u32(const void* p) {
    uint32_t a;
    asm("{ .reg .u64 t; cvta.to.shared.u64 t, %1; cvt.u32.u64 %0, t; }" : "=r"(a) : "l"(p));
    return a;
}

// ---------------- merged prep: packx+pool | w3 pack | w1 pack | border ----------------
// grid.x = 3584 (packx) + 64 (w3) + 16 (w1) + 32 (border) = 3696, 256 threads.
#define PREP_PACKX 3584
#define PREP_W3    (PREP_PACKX + 64)
#define PREP_W1    (PREP_W3 + 16)
#define PREP_TOTAL (PREP_W1 + 32)

__global__ void __launch_bounds__(256) prep(const float* __restrict__ x,
                                            const float* __restrict__ w3,
                                            const float* __restrict__ w1) {
    __shared__ float    s_pool[7*256];
    __shared__ uint32_t s_s8[28*65];

    int gid = blockIdx.x;
    int tid = threadIdx.x;

    if (gid < PREP_PACKX) {
        // ---- packx8_pool role (proven R9 code; gid = ((b*28)+i)*4+tile) ----
        int tile = gid & 3;
        int rest = gid >> 2;
        int i = rest % 28;
        int b = rest / 28;
        int wid = tid >> 5, lane = tid & 31;

        int r = lane / 14;
        int q = lane - r*14;
        bool active = (lane < 28);
        int rr = active ? r : 0;
        int row = 2*i + rr;
        int col = tile*14 + q;

        const float* xp = x + (((size_t)b*C + wid*32)*H + row)*H + col;

        uint32_t pk = 0;
        #pragma unroll
        for (int k = 0; k < 32; k++) {
            float v = active ? xp[(size_t)k*H*H] : 0.f;
            int s = (v > 0.f) - (v < 0.f);
            pk |= ((uint32_t)(uint8_t)(int8_t)s) << ((k & 3)*8);
            if ((k & 3) == 3) {
                if (active) s_s8[lane*65 + wid*8 + (k >> 2)] = pk;
                pk = 0;
            }
            float rs = v  + __shfl_down_sync(0xffffffffu, v, 14);
            float ps = rs + __shfl_down_sync(0xffffffffu, rs, 1);
            if (lane < 14 && (lane & 1) == 0)
                s_pool[(lane >> 1)*256 + wid*32 + k] = ps * 0.25f;
        }
        __syncthreads();

        for (int idx = tid; idx < 28*64; idx += 256) {
            int p = idx >> 6, c4 = idx & 63;
            int pr = p / 14, pq = p - pr*14;
            size_t rb = (((size_t)b*HP + (2*i + pr + 1))*HP + (tile*14 + pq + 1))*64;
            g_x8u[rb + c4] = s_s8[p*65 + c4];
        }
        for (int idx = tid; idx < 7*256; idx += 256) {
            int jl = idx >> 8, c = idx & 255;
            g_pool[ (((size_t)b*OH + i)*OH + tile*7 + jl)*C + c ] = s_pool[idx];
        }
    } else if (gid < PREP_W3) {
        // ---- w3 pack role, coalesced: thread = (co, ci4), 36 contiguous floats ----
        int t = (gid - PREP_PACKX)*256 + tid;   // 0..16383
        int co  = t >> 6;
        int ci4 = t & 63;
        const float* p = w3 + ((size_t)co*256 + ci4*4)*9;
        // per-tap sign-packed u32 (4 channel bytes)
        int chq   = ci4 >> 3;
        int rhigh = (ci4 >> 2) & 1;
        int tg    = ci4 & 3;
        int mt    = co >> 4;
        int g     = co & 7;
        int rlow  = (co >> 3) & 1;
        int rr2   = rhigh*2 + rlow;
        int lane  = g*4 + tg;
        #pragma unroll
        for (int tap = 0; tap < 9; tap++) {
            uint32_t pk = 0;
            #pragma unroll
            for (int z = 0; z < 4; z++) {
                float v = p[(size_t)z*9 + tap];
                int s = (v > 0.f) - (v < 0.f);
                pk |= ((uint32_t)(uint8_t)(int8_t)s) << (z*8);
            }
            int k32 = tap*8 + chq;
            g_w3f[ (((size_t)k32*16 + mt)*32 + lane)*4 + rr2 ] = pk;
        }
    } else if (gid < PREP_W1) {
        // ---- w1 bit-pack role ----
        int t = (gid - PREP_W3)*256 + tid;      // 0..4095
        int co = t >> 3, word = t & 7;
        const float* p = w1 + (size_t)co*C + word*32;
        uint32_t bits = 0;
        #pragma unroll
        for (int j = 0; j < 32; j++)
            if (p[j] > 0.f) bits |= (1u << j);
        g_w1bits[t] = bits;
    } else {
        // ---- border-zero role ----
        int b = gid - PREP_W1;
        size_t base = (size_t)b*HP*HP*64;
        for (int i = tid; i < HP*64; i += 256) {
            g_x8u[base + i] = 0;
            g_x8u[base + (size_t)(HP-1)*HP*64 + i] = 0;
        }
        for (int i = tid; i < (HP-2)*64; i += 256) {
            int r = i >> 6, c = i & 63;
            g_x8u[base + (size_t)(r+1)*HP*64 + c] = 0;
            g_x8u[base + (size_t)(r+1)*HP*64 + (HP-1)*64 + c] = 0;
        }
    }
}

// ---------------- IMMA conv3x3 + BN + pool + XNOR 1x1 + BN + concat ----------------
// PROVEN R13 kernel: 64 pixels x 256 co, 256 threads, cp.async 4-buffer depth-3,
// LDS.128 A-frags, ldmatrix.x4 B-frags. Epilogue in-place in the dots region.
#define WBUF_SZ 16384                   // 2 k32-steps x [mt16][lane32][16B]
#define XBUF_SZ (64*80)                 // 64 pix rows, 80B stride (64B data)
#define BUF_SZ  (WBUF_SZ + XBUF_SZ)     // 21504
#define OFF_SHB (256*66*4)              // 67584 (dots/h region)
#define SMEM_BYTES (4*BUF_SZ)           // 86016 (>= 67584 + 2304 epilogue)

__global__ void __launch_bounds__(256, 2) conv_mma(
    const float* __restrict__ g3, const float* __restrict__ b3,
    const float* __restrict__ m3, const float* __restrict__ v3,
    const float* __restrict__ g1, const float* __restrict__ b1,
    const float* __restrict__ m1, const float* __restrict__ v1,
    float* __restrict__ out)
{
    extern __shared__ __align__(16) char smem[];
    uint32_t sb = smem_u32(smem);
    int tid = threadIdx.x, wid = tid >> 5, lane = tid & 31;
    int g = lane >> 2, tg = lane & 3;
    int p0 = blockIdx.x * 64;

    // staging geometry: thread t stages pixel t>>2, 16B-quarter t&3
    int pixrel = tid >> 2;
    int zi = tid & 3;
    int pixs = p0 + pixrel;
    int bbs = pixs / 784;
    int rms = pixs - bbs*784;
    int iis = rms / 28;
    int jjs = rms - iis*28;
    const char* xrow = (const char*)g_x8u + ((((size_t)bbs*HP + 2*iis)*HP + 2*jjs) << 8);

    // ldmatrix per-lane row offsets: matrix mi = lane>>3, row ri = lane&7.
    int mi = lane >> 3, ri = lane & 7;
    uint32_t loff[4];
    #pragma unroll
    for (int q = 0; q < 4; q++)
        loff[q] = (uint32_t)(((2*q + (mi >> 1))*8 + ri)*80 + (mi & 1)*16);

    int acc[2][8][4];
    #pragma unroll
    for (int m = 0; m < 2; m++)
        #pragma unroll
        for (int n = 0; n < 8; n++)
            #pragma unroll
            for (int k = 0; k < 4; k++) acc[m][n][k] = 0;

    #define ISSUE(s) do { \
        int tap_ = (s) >> 2, chunk_ = (s) & 3; \
        int kh_ = tap_ / 3, kw_ = tap_ - kh_*3; \
        uint32_t bd = sb + ((s) & 3)*BUF_SZ; \
        const char* ws_ = (const char*)g_w3f + (size_t)(s)*16384; \
        cpa16(bd + (uint32_t)tid*16,         ws_ + (size_t)tid*16); \
        cpa16(bd + (uint32_t)(tid+256)*16,   ws_ + (size_t)(tid+256)*16); \
        cpa16(bd + (uint32_t)(tid+512)*16,   ws_ + (size_t)(tid+512)*16); \
        cpa16(bd + (uint32_t)(tid+768)*16,   ws_ + (size_t)(tid+768)*16); \
        cpa16(bd + WBUF_SZ + (uint32_t)pixrel*80 + zi*16, \
              xrow + (kh_*HP + kw_)*256 + chunk_*64 + zi*16); \
    } while (0)

    ISSUE(0); CP_COMMIT();
    ISSUE(1); CP_COMMIT();
    ISSUE(2); CP_COMMIT();

    for (int s = 0; s < 36; s++) {
        CP_WAIT2();
        __syncthreads();
        if (s + 3 < 36) ISSUE(s + 3);
        CP_COMMIT();

        const char* Bf = smem + (s & 3)*BUF_SZ;
        uint32_t XbU = sb + (s & 3)*BUF_SZ + WBUF_SZ;
        #pragma unroll
        for (int ks = 0; ks < 2; ks++) {
            uint32_t a[2][4], b[8][2];
            #pragma unroll
            for (int m = 0; m < 2; m++) {
                uint4 av = *(const uint4*)(Bf + ks*8192 + (wid*2 + m)*512 + lane*16);
                a[m][0] = av.x; a[m][1] = av.y; a[m][2] = av.z; a[m][3] = av.w;
            }
            #pragma unroll
            for (int q = 0; q < 4; q++)
                ldsm4(b[2*q][0], b[2*q][1], b[2*q+1][0], b[2*q+1][1],
                      XbU + loff[q] + ks*32);
            #pragma unroll
            for (int m = 0; m < 2; m++)
                #pragma unroll
                for (int n = 0; n < 8; n++)
                    mma_s8(acc[m][n], a[m], b[n]);
        }
    }
    __syncthreads();   // buffers dead; dots region reusable

    // ---- frag dump: acc -> s_dots[co][66] ----
    uint32_t* s_dots = (uint32_t*)smem;
    int m0 = wid*32;
    #pragma unroll
    for (int m = 0; m < 2; m++) {
        int co = m0 + m*16 + g;
        #pragma unroll
        for (int n = 0; n < 8; n++) {
            int px = n*8 + tg*2;
            *(uint2*)&s_dots[co*66 + px]     = make_uint2((uint32_t)acc[m][n][0], (uint32_t)acc[m][n][1]);
            *(uint2*)&s_dots[(co+8)*66 + px] = make_uint2((uint32_t)acc[m][n][2], (uint32_t)acc[m][n][3]);
        }
    }
    __syncthreads();

    // ---- pass2: BN3 + pool shortcut, h written IN PLACE; sign bits ----
    float* s_hf = (float*)smem;
    uint32_t* s_hb = (uint32_t*)(smem + OFF_SHB);
    {
        int co = tid;
        float inv = g3[co] * rsqrtf(v3[co] + EPSV);
        float add = b3[co] - m3[co]*inv;
        #pragma unroll 4
        for (int px = 0; px < 64; px++) {
            int dot = (int)s_dots[co*66 + px];
            float hv = (float)dot*inv + add + g_pool[(size_t)(p0 + px)*C + co];
            s_hf[co*66 + px] = hv;
            uint32_t mk = __ballot_sync(0xffffffffu, hv > 0.f);
            if (lane == 0) s_hb[px*9 + wid] = mk;
        }
    }
    __syncthreads();

    // ---- phase C: XNOR 1x1 + BN + concat(h,h) ----
    uint32_t hb[2][8];
    #pragma unroll
    for (int pg = 0; pg < 2; pg++)
        #pragma unroll
        for (int w = 0; w < 8; w++)
            hb[pg][w] = s_hb[(pg*32 + lane)*9 + w];

    size_t ob[2];
    #pragma unroll
    for (int pg = 0; pg < 2; pg++) {
        int p = p0 + pg*32 + lane;
        int b2 = p / 784;
        int rm2 = p - b2*784;
        ob[pg] = (size_t)b2*512*784 + rm2;
    }

    const uint4* wtab = (const uint4*)g_w1bits;
    for (int co2 = wid; co2 < 512; co2 += 8) {
        uint4 w0  = __ldg(wtab + co2*2);
        uint4 w1q = __ldg(wtab + co2*2 + 1);
        float i1 = __ldg(g1 + co2) * rsqrtf(__ldg(v1 + co2) + EPSV);
        float a1 = __ldg(b1 + co2) - __ldg(m1 + co2)*i1;
        int hc = co2 & 255;
        #pragma unroll
        for (int pg = 0; pg < 2; pg++) {
            int P = 0;
            P += __popc(hb[pg][0] ^ w0.x);  P += __popc(hb[pg][1] ^ w0.y);
            P += __popc(hb[pg][2] ^ w0.z);  P += __popc(hb[pg][3] ^ w0.w);
            P += __popc(hb[pg][4] ^ w1q.x); P += __popc(hb[pg][5] ^ w1q.y);
            P += __popc(hb[pg][6] ^ w1q.z); P += __popc(hb[pg][7] ^ w1q.w);
            float hv = s_hf[hc*66 + pg*32 + lane];
            out[ob[pg] + (size_t)co2*784] = (float)(256 - 2*P)*i1 + a1 + hv;
        }
    }
}

// ---------------- launch ----------------
extern "C" void kernel_launch(void* const* d_in, const int* in_sizes, int n_in,
                              void* d_out, int out_size) {
    const float* x  = (const float*)d_in[0];
    const float* w3 = (const float*)d_in[1];
    const float* g3 = (const float*)d_in[2];
    const float* b3 = (const float*)d_in[3];
    const float* m3 = (const float*)d_in[4];
    const float* v3 = (const float*)d_in[5];
    const float* w1 = (const float*)d_in[6];
    const float* g1 = (const float*)d_in[7];
    const float* b1 = (const float*)d_in[8];
    const float* m1 = (const float*)d_in[9];
    const float* v1 = (const float*)d_in[10];
    float* out = (float*)d_out;

    cudaFuncSetAttribute(conv_mma, cudaFuncAttributeMaxDynamicSharedMemorySize, SMEM_BYTES);

    prep<<<PREP_TOTAL, 256>>>(x, w3, w1);
    conv_mma<<<NBLK, 256, SMEM_BYTES>>>(g3, b3, m3, v3, g1, b1, m1, v1, out);
}